// round 1
// baseline (speedup 1.0000x reference)
#include <cuda_runtime.h>
#include <cstdint>

#define N_NODES 50000
#define N_EDGES 800000
#define NF 128
#define TILE 64
#define NTHREADS 256
#define NTILES (N_EDGES / TILE)   // 12500 exactly

#define S2_C 0.7071067811865475f
#define S2_3_C 0.4082482904638631f
#define INV_SQRT_MUL_C 0.17677669529663687f

// ---- shared memory layout (float offsets) ----
#define OFF_W1 0            // 32x64
#define OFF_B1 2048         // 64
#define OFF_W2 2112         // 64x32
#define OFF_B2 4160         // 32
#define OFF_W3 4192         // 32x128
#define OFF_B3 8288         // 128
// union region (phase A: sE/sH1/sH2, phase B: sX)
#define OFF_SE  8416                 // 64 x 33 (padded)
#define OFF_SH1 (8416 + 2112)        // 64 x 65 (padded)
#define OFF_SH2 (8416 + 6272)        // 64 x 33 (padded)
#define OFF_SX  8416                 // 64 x 128 (overlaps sE/sH1/sH2)
#define OFF_SW  16800                // 64 x 132 (padded)
#define OFF_SRC 25248                // 64 ints
#define OFF_DST 25312                // 64 ints
#define OFF_EF  25376                // 64 x 4 floats
#define SMEM_FLOATS 25632            // ~100.1 KB

__device__ __forceinline__ float silu_f(float x) {
    return x * (1.0f / (1.0f + __expf(-x)));
}

extern __shared__ float sm[];

__global__ __launch_bounds__(NTHREADS, 2)
void tfn_edge_kernel(const int* __restrict__ edge_index,
                     const float* __restrict__ node_feat,
                     const float* __restrict__ edge_feat,
                     const float* __restrict__ edge_embed,
                     const float* __restrict__ w1, const float* __restrict__ b1,
                     const float* __restrict__ w2, const float* __restrict__ b2,
                     const float* __restrict__ w3, const float* __restrict__ b3,
                     float* __restrict__ out)
{
    const int t = threadIdx.x;

    // ---- load MLP weights to SMEM once per CTA ----
    for (int i = t; i < 2048; i += NTHREADS) sm[OFF_W1 + i] = w1[i];
    for (int i = t; i < 64;   i += NTHREADS) sm[OFF_B1 + i] = b1[i];
    for (int i = t; i < 2048; i += NTHREADS) sm[OFF_W2 + i] = w2[i];
    for (int i = t; i < 32;   i += NTHREADS) sm[OFF_B2 + i] = b2[i];
    for (int i = t; i < 4096; i += NTHREADS) sm[OFF_W3 + i] = w3[i];
    for (int i = t; i < 128;  i += NTHREADS) sm[OFF_B3 + i] = b3[i];

    int* sSrc = (int*)&sm[OFF_SRC];
    int* sDst = (int*)&sm[OFF_DST];

    for (int tile = blockIdx.x; tile < NTILES; tile += gridDim.x) {
        const int e0 = tile * TILE;

        __syncthreads();   // previous iteration's readers done; also covers weight load on iter 0

        // ---- load indices + edge features ----
        if (t < TILE) {
            sSrc[t] = edge_index[e0 + t];
            sDst[t] = edge_index[N_EDGES + e0 + t];
            ((float4*)&sm[OFF_EF])[t] = ((const float4*)edge_feat)[e0 + t];
        }
        // ---- load embed tile (64x32) ----
        {
            const float4* g = (const float4*)(edge_embed + (size_t)e0 * 32);
            for (int i = t; i < TILE * 32 / 4; i += NTHREADS) {
                float4 v = g[i];
                int fl = i * 4;
                int e = fl >> 5, k = fl & 31;
                float* d = &sm[OFF_SE + e * 33 + k];
                d[0] = v.x; d[1] = v.y; d[2] = v.z; d[3] = v.w;
            }
        }
        __syncthreads();

        // ---- GEMM1: (64x32) @ (32x64) -> silu -> sH1 ----
        {
            const int tr = t >> 4, tc = t & 15;   // 4 edges x 4 cols
            float acc[4][4];
            float4 bb = *(const float4*)&sm[OFF_B1 + 4 * tc];
            #pragma unroll
            for (int i = 0; i < 4; i++) { acc[i][0]=bb.x; acc[i][1]=bb.y; acc[i][2]=bb.z; acc[i][3]=bb.w; }
            #pragma unroll 8
            for (int k = 0; k < 32; k++) {
                float4 b4 = *(const float4*)&sm[OFF_W1 + k * 64 + 4 * tc];
                float a0 = sm[OFF_SE + (4*tr+0)*33 + k];
                float a1 = sm[OFF_SE + (4*tr+1)*33 + k];
                float a2 = sm[OFF_SE + (4*tr+2)*33 + k];
                float a3 = sm[OFF_SE + (4*tr+3)*33 + k];
                acc[0][0] += a0*b4.x; acc[0][1] += a0*b4.y; acc[0][2] += a0*b4.z; acc[0][3] += a0*b4.w;
                acc[1][0] += a1*b4.x; acc[1][1] += a1*b4.y; acc[1][2] += a1*b4.z; acc[1][3] += a1*b4.w;
                acc[2][0] += a2*b4.x; acc[2][1] += a2*b4.y; acc[2][2] += a2*b4.z; acc[2][3] += a2*b4.w;
                acc[3][0] += a3*b4.x; acc[3][1] += a3*b4.y; acc[3][2] += a3*b4.z; acc[3][3] += a3*b4.w;
            }
            #pragma unroll
            for (int i = 0; i < 4; i++)
                #pragma unroll
                for (int j = 0; j < 4; j++)
                    sm[OFF_SH1 + (4*tr+i)*65 + 4*tc + j] = silu_f(acc[i][j]);
        }
        __syncthreads();

        // ---- GEMM2: (64x64) @ (64x32) -> silu -> sH2 ----
        {
            const int tr = t >> 3, tc = t & 7;    // 2 edges x 4 cols
            float acc[2][4];
            float4 bb = *(const float4*)&sm[OFF_B2 + 4 * tc];
            #pragma unroll
            for (int i = 0; i < 2; i++) { acc[i][0]=bb.x; acc[i][1]=bb.y; acc[i][2]=bb.z; acc[i][3]=bb.w; }
            #pragma unroll 8
            for (int k = 0; k < 64; k++) {
                float4 b4 = *(const float4*)&sm[OFF_W2 + k * 32 + 4 * tc];
                float a0 = sm[OFF_SH1 + (2*tr+0)*65 + k];
                float a1 = sm[OFF_SH1 + (2*tr+1)*65 + k];
                acc[0][0] += a0*b4.x; acc[0][1] += a0*b4.y; acc[0][2] += a0*b4.z; acc[0][3] += a0*b4.w;
                acc[1][0] += a1*b4.x; acc[1][1] += a1*b4.y; acc[1][2] += a1*b4.z; acc[1][3] += a1*b4.w;
            }
            #pragma unroll
            for (int i = 0; i < 2; i++)
                #pragma unroll
                for (int j = 0; j < 4; j++)
                    sm[OFF_SH2 + (2*tr+i)*33 + 4*tc + j] = silu_f(acc[i][j]);
        }
        __syncthreads();

        // ---- GEMM3: (64x32) @ (32x128) -> sW ----
        {
            const int tr = t >> 4, tc = t & 15;   // 4 edges x 8 cols
            float acc[4][8];
            float4 bl = *(const float4*)&sm[OFF_B3 + 8 * tc];
            float4 bh = *(const float4*)&sm[OFF_B3 + 8 * tc + 4];
            #pragma unroll
            for (int i = 0; i < 4; i++) {
                acc[i][0]=bl.x; acc[i][1]=bl.y; acc[i][2]=bl.z; acc[i][3]=bl.w;
                acc[i][4]=bh.x; acc[i][5]=bh.y; acc[i][6]=bh.z; acc[i][7]=bh.w;
            }
            #pragma unroll 8
            for (int k = 0; k < 32; k++) {
                float4 c0 = *(const float4*)&sm[OFF_W3 + k * 128 + 8 * tc];
                float4 c1 = *(const float4*)&sm[OFF_W3 + k * 128 + 8 * tc + 4];
                float a[4];
                #pragma unroll
                for (int i = 0; i < 4; i++) a[i] = sm[OFF_SH2 + (4*tr+i)*33 + k];
                #pragma unroll
                for (int i = 0; i < 4; i++) {
                    acc[i][0] += a[i]*c0.x; acc[i][1] += a[i]*c0.y;
                    acc[i][2] += a[i]*c0.z; acc[i][3] += a[i]*c0.w;
                    acc[i][4] += a[i]*c1.x; acc[i][5] += a[i]*c1.y;
                    acc[i][6] += a[i]*c1.z; acc[i][7] += a[i]*c1.w;
                }
            }
            #pragma unroll
            for (int i = 0; i < 4; i++) {
                float* d = &sm[OFF_SW + (4*tr+i)*132 + 8*tc];
                *(float4*)(d)     = make_float4(acc[i][0], acc[i][1], acc[i][2], acc[i][3]);
                *(float4*)(d + 4) = make_float4(acc[i][4], acc[i][5], acc[i][6], acc[i][7]);
            }
        }
        __syncthreads();

        // ---- gather x = node_feat[src] into sX (coalesced 512B row fetches) ----
        {
            const int w = t >> 5, l = t & 31;
            #pragma unroll
            for (int e = w; e < TILE; e += 8) {
                const float4* srcp = (const float4*)(node_feat + (size_t)sSrc[e] * NF);
                ((float4*)&sm[OFF_SX + e * NF])[l] = __ldg(&srcp[l]);
            }
        }
        __syncthreads();

        // ---- message construction + vector atomic scatter ----
        {
            const int w = t >> 5, l = t & 31;     // one warp = one edge, lane = 4-col chunk
            const int c = 4 * l;
            #pragma unroll
            for (int e = w; e < TILE; e += 8) {
                float4 ef = ((const float4*)&sm[OFF_EF])[e];   // e0, e1x, e1y, e1z
                const float* X = &sm[OFF_SX + e * NF];
                const float* W = &sm[OFF_SW + e * 132];
                float v0, v1, v2, v3;
                if (l < 8) {
                    // out0 channels: cols c..c+3 (< 32), u == col
                    float r[4];
                    #pragma unroll
                    for (int i = 0; i < 4; i++) {
                        int u = c + i;
                        float dot = X[32+3*u]*ef.y + X[33+3*u]*ef.z + X[34+3*u]*ef.w;
                        r[i] = S2_C * W[u] * X[u] * ef.x + S2_3_C * W[96+u] * dot;
                    }
                    v0 = r[0]; v1 = r[1]; v2 = r[2]; v3 = r[3];
                } else {
                    // out1 channels: cols c..c+3 (>= 32); m = col-32; u = m/3; j = m%3
                    float4 xv = *(const float4*)&X[c];   // x1[u][j] == x[col]
                    float r[4];
                    float xs[4] = {xv.x, xv.y, xv.z, xv.w};
                    #pragma unroll
                    for (int i = 0; i < 4; i++) {
                        int m = c + i - 32;
                        int u = (int)((unsigned)m / 3u);
                        int j = m - 3 * u;
                        float e1j = (j == 0) ? ef.y : ((j == 1) ? ef.z : ef.w);
                        r[i] = S2_C * W[32+u] * X[u] * e1j + S2_C * W[64+u] * xs[i] * ef.x;
                    }
                    v0 = r[0]; v1 = r[1]; v2 = r[2]; v3 = r[3];
                }
                float4* dstp = (float4*)(out + (size_t)sDst[e] * NF + c);
                atomicAdd(dstp, make_float4(v0, v1, v2, v3));   // sm_90+ 128-bit red
            }
        }
    }
}

// ---- self-connection: out[n] = concat(n0 @ sc_w0, einsum(n1, sc_w1)) * 1/sqrt(MUL) ----
__global__ __launch_bounds__(128)
void tfn_sc_kernel(const float* __restrict__ node_feat,
                   const float* __restrict__ sc_w0,
                   const float* __restrict__ sc_w1,
                   float* __restrict__ out)
{
    __shared__ float sx[128];
    const int c = threadIdx.x;   // output column 0..127
    float wreg[32];
    int j = 0;
    if (c < 32) {
        #pragma unroll
        for (int u = 0; u < 32; u++) wreg[u] = sc_w0[u * 32 + c];
    } else {
        int m = c - 32;
        int v = m / 3;
        j = m - 3 * v;
        #pragma unroll
        for (int u = 0; u < 32; u++) wreg[u] = sc_w1[u * 32 + v];
    }
    for (int n = blockIdx.x; n < N_NODES; n += gridDim.x) {
        __syncthreads();
        sx[c] = node_feat[(size_t)n * NF + c];
        __syncthreads();
        float acc = 0.0f;
        if (c < 32) {
            #pragma unroll
            for (int u = 0; u < 32; u++) acc += sx[u] * wreg[u];
        } else {
            #pragma unroll
            for (int u = 0; u < 32; u++) acc += sx[32 + 3*u + j] * wreg[u];
        }
        out[(size_t)n * NF + c] = acc * INV_SQRT_MUL_C;
    }
}

extern "C" void kernel_launch(void* const* d_in, const int* in_sizes, int n_in,
                              void* d_out, int out_size)
{
    const int*   edge_index = (const int*)d_in[0];
    const float* node_feat  = (const float*)d_in[1];
    const float* edge_feat  = (const float*)d_in[2];
    const float* edge_embed = (const float*)d_in[3];
    const float* fc_w1 = (const float*)d_in[4];
    const float* fc_b1 = (const float*)d_in[5];
    const float* fc_w2 = (const float*)d_in[6];
    const float* fc_b2 = (const float*)d_in[7];
    const float* fc_w3 = (const float*)d_in[8];
    const float* fc_b3 = (const float*)d_in[9];
    const float* sc_w0 = (const float*)d_in[10];
    const float* sc_w1 = (const float*)d_in[11];
    float* out = (float*)d_out;

    // 1) initialize output with self-connection term
    tfn_sc_kernel<<<2048, 128>>>(node_feat, sc_w0, sc_w1, out);

    // 2) fused edge MLP + message + scatter-add (atomics on top of init)
    const size_t smem_bytes = SMEM_FLOATS * sizeof(float);
    cudaFuncSetAttribute(tfn_edge_kernel,
                         cudaFuncAttributeMaxDynamicSharedMemorySize,
                         (int)smem_bytes);
    tfn_edge_kernel<<<304, NTHREADS, smem_bytes>>>(
        edge_index, node_feat, edge_feat, edge_embed,
        fc_w1, fc_b1, fc_w2, fc_b2, fc_w3, fc_b3, out);
}

// round 2
// speedup vs baseline: 1.0540x; 1.0540x over previous
#include <cuda_runtime.h>
#include <cstdint>

#define N_NODES 50000
#define N_EDGES 800000
#define NF 128
#define TILE 64
#define NTHREADS 256
#define NTILES (N_EDGES / TILE)   // 12500 exactly

#define S2_C 0.7071067811865475f
#define S2_3_C 0.4082482904638631f
#define INV_SQRT_MUL_C 0.17677669529663687f

// ---- shared memory layout (float offsets) ----
// weights
#define OFF_W1 0            // 32x64
#define OFF_B1 2048         // 64
#define OFF_W2 2112         // 64x32
#define OFF_B2 4160         // 32
#define OFF_W3 4192         // 32x128
#define OFF_B3 8288         // 128
// activations (padded strides, multiples of 4 floats for LDS.128)
#define SE_STRIDE  36
#define SH1_STRIDE 68
#define SH2_STRIDE 36
#define OFF_SE  8416                     // 64 x 36 = 2304
#define OFF_SH1 (OFF_SE + 64*SE_STRIDE)  // 10720: 64 x 68 = 4352
#define OFF_SH2 (OFF_SH1 + 64*SH1_STRIDE)// 15072: 64 x 36 = 2304 -> end 17376
#define OFF_SX  OFF_SE                   // 64 x 128 = 8192 (union with SE/SH1/SH2)
#define OFF_SW  17376                    // 64 x 132 = 8448
#define OFF_SRC 25824                    // 64 ints
#define OFF_DST 25888                    // 64 ints
#define OFF_EF  25952                    // 64 x 4
#define SMEM_FLOATS 26208                // ~102.4 KB -> 2 CTAs/SM

__device__ __forceinline__ float silu_f(float x) {
    return x * (1.0f / (1.0f + __expf(-x)));
}

extern __shared__ float sm[];

__global__ __launch_bounds__(NTHREADS, 2)
void tfn_edge_kernel(const int* __restrict__ edge_index,
                     const float* __restrict__ node_feat,
                     const float* __restrict__ edge_feat,
                     const float* __restrict__ edge_embed,
                     const float* __restrict__ w1, const float* __restrict__ b1,
                     const float* __restrict__ w2, const float* __restrict__ b2,
                     const float* __restrict__ w3, const float* __restrict__ b3,
                     float* __restrict__ out)
{
    const int t = threadIdx.x;

    // ---- load MLP weights to SMEM once per CTA ----
    for (int i = t; i < 512; i += NTHREADS) ((float4*)&sm[OFF_W1])[i] = ((const float4*)w1)[i];
    for (int i = t; i < 16;  i += NTHREADS) ((float4*)&sm[OFF_B1])[i] = ((const float4*)b1)[i];
    for (int i = t; i < 512; i += NTHREADS) ((float4*)&sm[OFF_W2])[i] = ((const float4*)w2)[i];
    for (int i = t; i < 8;   i += NTHREADS) ((float4*)&sm[OFF_B2])[i] = ((const float4*)b2)[i];
    for (int i = t; i < 1024;i += NTHREADS) ((float4*)&sm[OFF_W3])[i] = ((const float4*)w3)[i];
    for (int i = t; i < 32;  i += NTHREADS) ((float4*)&sm[OFF_B3])[i] = ((const float4*)b3)[i];

    int* sSrc = (int*)&sm[OFF_SRC];
    int* sDst = (int*)&sm[OFF_DST];

    for (int tile = blockIdx.x; tile < NTILES; tile += gridDim.x) {
        const int e0 = tile * TILE;

        __syncthreads();   // previous iteration's readers done; also covers weight load on iter 0

        // ---- load indices + edge features ----
        if (t < TILE) {
            sSrc[t] = edge_index[e0 + t];
            sDst[t] = edge_index[N_EDGES + e0 + t];
            ((float4*)&sm[OFF_EF])[t] = ((const float4*)edge_feat)[e0 + t];
        }
        // ---- load embed tile (64x32) ----
        {
            const float4* g = (const float4*)(edge_embed + (size_t)e0 * 32);
            #pragma unroll
            for (int i = t; i < TILE * 32 / 4; i += NTHREADS) {
                float4 v = g[i];
                int fl = i * 4;
                int e = fl >> 5, k = fl & 31;              // k multiple of 4
                *(float4*)&sm[OFF_SE + e * SE_STRIDE + k] = v;
            }
        }
        __syncthreads();

        // ---- GEMM1: (64x32) @ (32x64) -> silu -> sH1 ----
        {
            const int tr = t >> 4, tc = t & 15;   // 4 edges x 4 cols
            float acc[4][4];
            float4 bb = *(const float4*)&sm[OFF_B1 + 4 * tc];
            #pragma unroll
            for (int i = 0; i < 4; i++) { acc[i][0]=bb.x; acc[i][1]=bb.y; acc[i][2]=bb.z; acc[i][3]=bb.w; }
            #pragma unroll
            for (int k4 = 0; k4 < 8; k4++) {
                float4 a4[4];
                #pragma unroll
                for (int i = 0; i < 4; i++)
                    a4[i] = *(const float4*)&sm[OFF_SE + (4*tr+i)*SE_STRIDE + 4*k4];
                #pragma unroll
                for (int kk = 0; kk < 4; kk++) {
                    float4 b4 = *(const float4*)&sm[OFF_W1 + (4*k4+kk) * 64 + 4 * tc];
                    #pragma unroll
                    for (int i = 0; i < 4; i++) {
                        float a = (kk==0)?a4[i].x:(kk==1)?a4[i].y:(kk==2)?a4[i].z:a4[i].w;
                        acc[i][0] += a*b4.x; acc[i][1] += a*b4.y;
                        acc[i][2] += a*b4.z; acc[i][3] += a*b4.w;
                    }
                }
            }
            #pragma unroll
            for (int i = 0; i < 4; i++) {
                float4 v = make_float4(silu_f(acc[i][0]), silu_f(acc[i][1]),
                                       silu_f(acc[i][2]), silu_f(acc[i][3]));
                *(float4*)&sm[OFF_SH1 + (4*tr+i)*SH1_STRIDE + 4*tc] = v;
            }
        }
        __syncthreads();

        // ---- GEMM2: (64x64) @ (64x32) -> silu -> sH2 ----
        {
            const int tr = t >> 3, tc = t & 7;    // 2 edges x 4 cols
            float acc[2][4];
            float4 bb = *(const float4*)&sm[OFF_B2 + 4 * tc];
            #pragma unroll
            for (int i = 0; i < 2; i++) { acc[i][0]=bb.x; acc[i][1]=bb.y; acc[i][2]=bb.z; acc[i][3]=bb.w; }
            #pragma unroll
            for (int k4 = 0; k4 < 16; k4++) {
                float4 a4[2];
                #pragma unroll
                for (int i = 0; i < 2; i++)
                    a4[i] = *(const float4*)&sm[OFF_SH1 + (2*tr+i)*SH1_STRIDE + 4*k4];
                #pragma unroll
                for (int kk = 0; kk < 4; kk++) {
                    float4 b4 = *(const float4*)&sm[OFF_W2 + (4*k4+kk) * 32 + 4 * tc];
                    #pragma unroll
                    for (int i = 0; i < 2; i++) {
                        float a = (kk==0)?a4[i].x:(kk==1)?a4[i].y:(kk==2)?a4[i].z:a4[i].w;
                        acc[i][0] += a*b4.x; acc[i][1] += a*b4.y;
                        acc[i][2] += a*b4.z; acc[i][3] += a*b4.w;
                    }
                }
            }
            #pragma unroll
            for (int i = 0; i < 2; i++) {
                float4 v = make_float4(silu_f(acc[i][0]), silu_f(acc[i][1]),
                                       silu_f(acc[i][2]), silu_f(acc[i][3]));
                *(float4*)&sm[OFF_SH2 + (2*tr+i)*SH2_STRIDE + 4*tc] = v;
            }
        }
        __syncthreads();

        // ---- GEMM3: (64x32) @ (32x128) -> sW ----
        {
            const int tr = t >> 4, tc = t & 15;   // 4 edges x 8 cols
            float acc[4][8];
            float4 bl = *(const float4*)&sm[OFF_B3 + 8 * tc];
            float4 bh = *(const float4*)&sm[OFF_B3 + 8 * tc + 4];
            #pragma unroll
            for (int i = 0; i < 4; i++) {
                acc[i][0]=bl.x; acc[i][1]=bl.y; acc[i][2]=bl.z; acc[i][3]=bl.w;
                acc[i][4]=bh.x; acc[i][5]=bh.y; acc[i][6]=bh.z; acc[i][7]=bh.w;
            }
            #pragma unroll
            for (int k4 = 0; k4 < 8; k4++) {
                float4 a4[4];
                #pragma unroll
                for (int i = 0; i < 4; i++)
                    a4[i] = *(const float4*)&sm[OFF_SH2 + (4*tr+i)*SH2_STRIDE + 4*k4];
                #pragma unroll
                for (int kk = 0; kk < 4; kk++) {
                    float4 c0 = *(const float4*)&sm[OFF_W3 + (4*k4+kk) * 128 + 8 * tc];
                    float4 c1 = *(const float4*)&sm[OFF_W3 + (4*k4+kk) * 128 + 8 * tc + 4];
                    #pragma unroll
                    for (int i = 0; i < 4; i++) {
                        float a = (kk==0)?a4[i].x:(kk==1)?a4[i].y:(kk==2)?a4[i].z:a4[i].w;
                        acc[i][0] += a*c0.x; acc[i][1] += a*c0.y;
                        acc[i][2] += a*c0.z; acc[i][3] += a*c0.w;
                        acc[i][4] += a*c1.x; acc[i][5] += a*c1.y;
                        acc[i][6] += a*c1.z; acc[i][7] += a*c1.w;
                    }
                }
            }
            #pragma unroll
            for (int i = 0; i < 4; i++) {
                float* d = &sm[OFF_SW + (4*tr+i)*132 + 8*tc];
                *(float4*)(d)     = make_float4(acc[i][0], acc[i][1], acc[i][2], acc[i][3]);
                *(float4*)(d + 4) = make_float4(acc[i][4], acc[i][5], acc[i][6], acc[i][7]);
            }
        }
        __syncthreads();

        // ---- gather x = node_feat[src] into sX (coalesced 512B row fetches) ----
        {
            const int w = t >> 5, l = t & 31;
            #pragma unroll
            for (int e = w; e < TILE; e += 8) {
                const float4* srcp = (const float4*)(node_feat + (size_t)sSrc[e] * NF);
                ((float4*)&sm[OFF_SX + e * NF])[l] = __ldg(&srcp[l]);
            }
        }
        __syncthreads();

        // ---- message construction + vector atomic scatter ----
        {
            const int w = t >> 5, l = t & 31;     // one warp = one edge, lane = 4-col chunk
            const int c = 4 * l;
            #pragma unroll
            for (int e = w; e < TILE; e += 8) {
                float4 ef = ((const float4*)&sm[OFF_EF])[e];   // e0, e1x, e1y, e1z
                const float* X = &sm[OFF_SX + e * NF];
                const float* W = &sm[OFF_SW + e * 132];
                float4 res;
                if (l < 8) {
                    // out0: cols c..c+3 (<32), u == col
                    float4 w000 = *(const float4*)&W[c];
                    float4 w110 = *(const float4*)&W[96 + c];
                    float4 x0v  = *(const float4*)&X[c];
                    float4 xa = *(const float4*)&X[32 + 12*l];
                    float4 xb = *(const float4*)&X[32 + 12*l + 4];
                    float4 xc = *(const float4*)&X[32 + 12*l + 8];
                    float d0 = xa.x*ef.y + xa.y*ef.z + xa.z*ef.w;
                    float d1 = xa.w*ef.y + xb.x*ef.z + xb.y*ef.w;
                    float d2 = xb.z*ef.y + xb.w*ef.z + xc.x*ef.w;
                    float d3 = xc.y*ef.y + xc.z*ef.z + xc.w*ef.w;
                    res.x = S2_C * w000.x * x0v.x * ef.x + S2_3_C * w110.x * d0;
                    res.y = S2_C * w000.y * x0v.y * ef.x + S2_3_C * w110.y * d1;
                    res.z = S2_C * w000.z * x0v.z * ef.x + S2_3_C * w110.z * d2;
                    res.w = S2_C * w000.w * x0v.w * ef.x + S2_3_C * w110.w * d3;
                } else {
                    // out1: cols c..c+3 (>=32); m = col-32; u = m/3; j = m%3
                    const int m0 = c - 32;
                    const int ua = m0 / 3;             // consecutive m0..m0+3 span ua, ua+1
                    float4 x1v = *(const float4*)&X[c];
                    float w011a = W[32 + ua], w011b = W[32 + ua + 1];
                    float w101a = W[64 + ua], w101b = W[64 + ua + 1];
                    float x0a = X[ua], x0b = X[ua + 1];
                    float r[4];
                    float xs[4] = {x1v.x, x1v.y, x1v.z, x1v.w};
                    #pragma unroll
                    for (int i = 0; i < 4; i++) {
                        int m = m0 + i;
                        int u = m / 3;
                        int j = m - 3 * u;
                        bool hi = (u != ua);
                        float e1j = (j == 0) ? ef.y : ((j == 1) ? ef.z : ef.w);
                        float w011 = hi ? w011b : w011a;
                        float w101 = hi ? w101b : w101a;
                        float x0u  = hi ? x0b  : x0a;
                        r[i] = S2_C * w011 * x0u * e1j + S2_C * w101 * xs[i] * ef.x;
                    }
                    res = make_float4(r[0], r[1], r[2], r[3]);
                }
                float4* dstp = (float4*)(out + (size_t)sDst[e] * NF + c);
                atomicAdd(dstp, res);   // sm_90+ 128-bit red
            }
        }
    }
}

// ---- self-connection: out[n] = concat(n0 @ sc_w0, einsum(n1, sc_w1)) * 1/sqrt(MUL) ----
__global__ __launch_bounds__(128)
void tfn_sc_kernel(const float* __restrict__ node_feat,
                   const float* __restrict__ sc_w0,
                   const float* __restrict__ sc_w1,
                   float* __restrict__ out)
{
    __shared__ float sx[128];
    const int c = threadIdx.x;   // output column 0..127
    float wreg[32];
    int j = 0;
    if (c < 32) {
        #pragma unroll
        for (int u = 0; u < 32; u++) wreg[u] = sc_w0[u * 32 + c];
    } else {
        int m = c - 32;
        int v = m / 3;
        j = m - 3 * v;
        #pragma unroll
        for (int u = 0; u < 32; u++) wreg[u] = sc_w1[u * 32 + v];
    }
    for (int n = blockIdx.x; n < N_NODES; n += gridDim.x) {
        __syncthreads();
        sx[c] = node_feat[(size_t)n * NF + c];
        __syncthreads();
        float acc = 0.0f;
        if (c < 32) {
            #pragma unroll
            for (int u = 0; u < 32; u++) acc += sx[u] * wreg[u];
        } else {
            #pragma unroll
            for (int u = 0; u < 32; u++) acc += sx[32 + 3*u + j] * wreg[u];
        }
        out[(size_t)n * NF + c] = acc * INV_SQRT_MUL_C;
    }
}

extern "C" void kernel_launch(void* const* d_in, const int* in_sizes, int n_in,
                              void* d_out, int out_size)
{
    const int*   edge_index = (const int*)d_in[0];
    const float* node_feat  = (const float*)d_in[1];
    const float* edge_feat  = (const float*)d_in[2];
    const float* edge_embed = (const float*)d_in[3];
    const float* fc_w1 = (const float*)d_in[4];
    const float* fc_b1 = (const float*)d_in[5];
    const float* fc_w2 = (const float*)d_in[6];
    const float* fc_b2 = (const float*)d_in[7];
    const float* fc_w3 = (const float*)d_in[8];
    const float* fc_b3 = (const float*)d_in[9];
    const float* sc_w0 = (const float*)d_in[10];
    const float* sc_w1 = (const float*)d_in[11];
    float* out = (float*)d_out;

    // 1) initialize output with self-connection term
    tfn_sc_kernel<<<2048, 128>>>(node_feat, sc_w0, sc_w1, out);

    // 2) fused edge MLP + message + scatter-add (atomics on top of init)
    const size_t smem_bytes = SMEM_FLOATS * sizeof(float);
    cudaFuncSetAttribute(tfn_edge_kernel,
                         cudaFuncAttributeMaxDynamicSharedMemorySize,
                         (int)smem_bytes);
    tfn_edge_kernel<<<304, NTHREADS, smem_bytes>>>(
        edge_index, node_feat, edge_feat, edge_embed,
        fc_w1, fc_b1, fc_w2, fc_b2, fc_w3, fc_b3, out);
}

// round 3
// speedup vs baseline: 1.6124x; 1.5297x over previous
#include <cuda_runtime.h>
#include <cstdint>

#define N_NODES 50000
#define N_EDGES 800000
#define NF 128
#define TILE 64
#define NTHREADS 256
#define NTILES (N_EDGES / TILE)   // 12500 exactly

#define S2_C 0.7071067811865475f
#define S2_3_C 0.4082482904638631f
#define INV_SQRT_MUL_C 0.17677669529663687f

// ---- shared memory layout (float offsets) ----
// precomputed tf32 B-fragments (fragment-linear, float2 per lane)
#define OFF_FB1 0            // 4kk x 8jg x 32 lanes x float2 = 2048 floats
#define OFF_FB2 2048         // 8kk x 4jg x 32 x float2     = 2048
#define OFF_FB3 4096         // 4kk x 16jg x 32 x float2    = 4096
#define OFF_B1  8192         // 64
#define OFF_B2  8256         // 32
#define OFF_B3  8288         // 128 -> 8416
// activations (conflict-free strides for fragment loads)
#define SE_STRIDE  36
#define SH1_STRIDE 68
#define SH2_STRIDE 36
#define OFF_SE  8416                      // 64 x 36 = 2304 -> 10720
#define OFF_SH1 10720                     // 64 x 68 = 4352 -> 15072
#define OFF_SH2 15072                     // 64 x 36 = 2304 -> 17376
#define OFF_SX  OFF_SE                    // 64 x 128 = 8192 (union w/ sE/sH1/sH2 = 8960)
#define OFF_SW  17376                     // 64 x 132 = 8448 -> 25824
#define OFF_SRC 25824                     // 64 ints
#define OFF_DST 25888                     // 64 ints
#define OFF_EF  25952                     // 64 x 4
#define SMEM_FLOATS 26208                 // ~104.8 KB -> 2 CTAs/SM

__device__ __forceinline__ float silu_f(float x) {
    return x * (1.0f / (1.0f + __expf(-x)));
}

// round-to-nearest tf32 conversion, returned as float bits
__device__ __forceinline__ float tf32f(float x) {
    uint32_t r;
    asm("cvt.rna.tf32.f32 %0, %1;" : "=r"(r) : "f"(x));
    return __uint_as_float(r);
}

__device__ __forceinline__ void mma_tf32(float c[4],
                                         uint32_t a0, uint32_t a1, uint32_t a2, uint32_t a3,
                                         uint32_t b0, uint32_t b1) {
    asm volatile("mma.sync.aligned.m16n8k8.row.col.f32.tf32.tf32.f32 "
                 "{%0,%1,%2,%3},{%4,%5,%6,%7},{%8,%9},{%0,%1,%2,%3};"
                 : "+f"(c[0]), "+f"(c[1]), "+f"(c[2]), "+f"(c[3])
                 : "r"(a0), "r"(a1), "r"(a2), "r"(a3), "r"(b0), "r"(b1));
}

extern __shared__ float sm[];

__global__ __launch_bounds__(NTHREADS, 2)
void tfn_edge_kernel(const int* __restrict__ edge_index,
                     const float* __restrict__ node_feat,
                     const float* __restrict__ edge_feat,
                     const float* __restrict__ edge_embed,
                     const float* __restrict__ w1, const float* __restrict__ b1,
                     const float* __restrict__ w2, const float* __restrict__ b2,
                     const float* __restrict__ w3, const float* __restrict__ b3,
                     float* __restrict__ out)
{
    const int t = threadIdx.x;
    const int w = t >> 5, lane = t & 31;
    const int g = lane >> 2, tig = lane & 3;
    const int mr = w >> 1, nc = w & 1;

    // ---- precompute tf32 B-fragments (once per CTA, straight from gmem/L2) ----
    // B frag layout (m16n8k8 col-major B): b0 = B[8kk+tig][8jg+g], b1 = B[8kk+tig+4][8jg+g]
    for (int i = t; i < 1024; i += NTHREADS) {       // W1: 32x64, kk 0..3, jg 0..7
        int kk = i >> 8, jg = (i >> 5) & 7, ln = i & 31;
        int gg = ln >> 2, tt = ln & 3;
        int k0 = 8*kk + tt, n = 8*jg + gg;
        ((float2*)&sm[OFF_FB1])[i] = make_float2(tf32f(w1[k0*64 + n]), tf32f(w1[(k0+4)*64 + n]));
    }
    for (int i = t; i < 1024; i += NTHREADS) {       // W2: 64x32, kk 0..7, jg 0..3
        int kk = i >> 7, jg = (i >> 5) & 3, ln = i & 31;
        int gg = ln >> 2, tt = ln & 3;
        int k0 = 8*kk + tt, n = 8*jg + gg;
        ((float2*)&sm[OFF_FB2])[i] = make_float2(tf32f(w2[k0*32 + n]), tf32f(w2[(k0+4)*32 + n]));
    }
    for (int i = t; i < 2048; i += NTHREADS) {       // W3: 32x128, kk 0..3, jg 0..15
        int kk = i >> 9, jg = (i >> 5) & 15, ln = i & 31;
        int gg = ln >> 2, tt = ln & 3;
        int k0 = 8*kk + tt, n = 8*jg + gg;
        ((float2*)&sm[OFF_FB3])[i] = make_float2(tf32f(w3[k0*128 + n]), tf32f(w3[(k0+4)*128 + n]));
    }
    for (int i = t; i < 64;  i += NTHREADS) sm[OFF_B1 + i] = b1[i];
    for (int i = t; i < 32;  i += NTHREADS) sm[OFF_B2 + i] = b2[i];
    for (int i = t; i < 128; i += NTHREADS) sm[OFF_B3 + i] = b3[i];

    int* sSrc = (int*)&sm[OFF_SRC];
    int* sDst = (int*)&sm[OFF_DST];

    for (int tile = blockIdx.x; tile < NTILES; tile += gridDim.x) {
        const int e0 = tile * TILE;

        __syncthreads();   // prev-iter readers done; also covers precompute on iter 0

        // ---- load indices + edge features ----
        if (t < TILE) {
            sSrc[t] = edge_index[e0 + t];
            sDst[t] = edge_index[N_EDGES + e0 + t];
            ((float4*)&sm[OFF_EF])[t] = ((const float4*)edge_feat)[e0 + t];
        }
        // ---- load embed tile (64x32), tf32-converted ----
        {
            const float4* gp = (const float4*)(edge_embed + (size_t)e0 * 32);
            #pragma unroll
            for (int i = t; i < TILE * 32 / 4; i += NTHREADS) {
                float4 v = gp[i];
                int fl = i * 4;
                int e = fl >> 5, k = fl & 31;
                *(float4*)&sm[OFF_SE + e * SE_STRIDE + k] =
                    make_float4(tf32f(v.x), tf32f(v.y), tf32f(v.z), tf32f(v.w));
            }
        }
        __syncthreads();

        // ---- GEMM1: (64x32)@(32x64) -> +bias -> silu -> tf32 -> sH1 ----
        {
            float c[4][4] = {{0,0,0,0},{0,0,0,0},{0,0,0,0},{0,0,0,0}};
            #pragma unroll
            for (int kk = 0; kk < 4; kk++) {
                const float* Ab = &sm[OFF_SE + (16*mr + g) * SE_STRIDE + 8*kk + tig];
                uint32_t a0 = __float_as_uint(Ab[0]);
                uint32_t a1 = __float_as_uint(Ab[8*SE_STRIDE]);
                uint32_t a2 = __float_as_uint(Ab[4]);
                uint32_t a3 = __float_as_uint(Ab[8*SE_STRIDE + 4]);
                #pragma unroll
                for (int j = 0; j < 4; j++) {
                    float2 b = ((const float2*)&sm[OFF_FB1])[(kk*8 + 4*nc + j)*32 + lane];
                    mma_tf32(c[j], a0, a1, a2, a3, __float_as_uint(b.x), __float_as_uint(b.y));
                }
            }
            #pragma unroll
            for (int j = 0; j < 4; j++) {
                int n0 = 32*nc + 8*j + 2*tig;
                float2 bb = *(const float2*)&sm[OFF_B1 + n0];
                int r0 = 16*mr + g;
                *(float2*)&sm[OFF_SH1 + r0*SH1_STRIDE + n0] =
                    make_float2(tf32f(silu_f(c[j][0] + bb.x)), tf32f(silu_f(c[j][1] + bb.y)));
                *(float2*)&sm[OFF_SH1 + (r0+8)*SH1_STRIDE + n0] =
                    make_float2(tf32f(silu_f(c[j][2] + bb.x)), tf32f(silu_f(c[j][3] + bb.y)));
            }
        }
        __syncthreads();

        // ---- GEMM2: (64x64)@(64x32) -> +bias -> silu -> tf32 -> sH2 ----
        {
            float c[2][4] = {{0,0,0,0},{0,0,0,0}};
            #pragma unroll
            for (int kk = 0; kk < 8; kk++) {
                const float* Ab = &sm[OFF_SH1 + (16*mr + g) * SH1_STRIDE + 8*kk + tig];
                uint32_t a0 = __float_as_uint(Ab[0]);
                uint32_t a1 = __float_as_uint(Ab[8*SH1_STRIDE]);
                uint32_t a2 = __float_as_uint(Ab[4]);
                uint32_t a3 = __float_as_uint(Ab[8*SH1_STRIDE + 4]);
                #pragma unroll
                for (int j = 0; j < 2; j++) {
                    float2 b = ((const float2*)&sm[OFF_FB2])[(kk*4 + 2*nc + j)*32 + lane];
                    mma_tf32(c[j], a0, a1, a2, a3, __float_as_uint(b.x), __float_as_uint(b.y));
                }
            }
            #pragma unroll
            for (int j = 0; j < 2; j++) {
                int n0 = 16*nc + 8*j + 2*tig;
                float2 bb = *(const float2*)&sm[OFF_B2 + n0];
                int r0 = 16*mr + g;
                *(float2*)&sm[OFF_SH2 + r0*SH2_STRIDE + n0] =
                    make_float2(tf32f(silu_f(c[j][0] + bb.x)), tf32f(silu_f(c[j][1] + bb.y)));
                *(float2*)&sm[OFF_SH2 + (r0+8)*SH2_STRIDE + n0] =
                    make_float2(tf32f(silu_f(c[j][2] + bb.x)), tf32f(silu_f(c[j][3] + bb.y)));
            }
        }
        __syncthreads();

        // ---- GEMM3: (64x32)@(32x128) -> +bias -> sW (fp32) ----
        {
            float c[8][4] = {{0,0,0,0},{0,0,0,0},{0,0,0,0},{0,0,0,0},
                             {0,0,0,0},{0,0,0,0},{0,0,0,0},{0,0,0,0}};
            #pragma unroll
            for (int kk = 0; kk < 4; kk++) {
                const float* Ab = &sm[OFF_SH2 + (16*mr + g) * SH2_STRIDE + 8*kk + tig];
                uint32_t a0 = __float_as_uint(Ab[0]);
                uint32_t a1 = __float_as_uint(Ab[8*SH2_STRIDE]);
                uint32_t a2 = __float_as_uint(Ab[4]);
                uint32_t a3 = __float_as_uint(Ab[8*SH2_STRIDE + 4]);
                #pragma unroll
                for (int j = 0; j < 8; j++) {
                    float2 b = ((const float2*)&sm[OFF_FB3])[(kk*16 + 8*nc + j)*32 + lane];
                    mma_tf32(c[j], a0, a1, a2, a3, __float_as_uint(b.x), __float_as_uint(b.y));
                }
            }
            #pragma unroll
            for (int j = 0; j < 8; j++) {
                int n0 = 64*nc + 8*j + 2*tig;
                float2 bb = *(const float2*)&sm[OFF_B3 + n0];
                int r0 = 16*mr + g;
                *(float2*)&sm[OFF_SW + r0*132 + n0] = make_float2(c[j][0] + bb.x, c[j][1] + bb.y);
                *(float2*)&sm[OFF_SW + (r0+8)*132 + n0] = make_float2(c[j][2] + bb.x, c[j][3] + bb.y);
            }
        }
        __syncthreads();

        // ---- gather x = node_feat[src] into sX (coalesced 512B row fetches) ----
        {
            #pragma unroll
            for (int e = w; e < TILE; e += 8) {
                const float4* srcp = (const float4*)(node_feat + (size_t)sSrc[e] * NF);
                ((float4*)&sm[OFF_SX + e * NF])[lane] = __ldg(&srcp[lane]);
            }
        }
        __syncthreads();

        // ---- message construction + vector atomic scatter ----
        {
            const int c = 4 * lane;
            #pragma unroll
            for (int e = w; e < TILE; e += 8) {
                float4 ef = ((const float4*)&sm[OFF_EF])[e];   // e0, e1x, e1y, e1z
                const float* X = &sm[OFF_SX + e * NF];
                const float* W = &sm[OFF_SW + e * 132];
                float4 res;
                if (lane < 8) {
                    // out0: cols c..c+3 (<32), u == col
                    float4 w000 = *(const float4*)&W[c];
                    float4 w110 = *(const float4*)&W[96 + c];
                    float4 x0v  = *(const float4*)&X[c];
                    float4 xa = *(const float4*)&X[32 + 12*lane];
                    float4 xb = *(const float4*)&X[32 + 12*lane + 4];
                    float4 xc = *(const float4*)&X[32 + 12*lane + 8];
                    float d0 = xa.x*ef.y + xa.y*ef.z + xa.z*ef.w;
                    float d1 = xa.w*ef.y + xb.x*ef.z + xb.y*ef.w;
                    float d2 = xb.z*ef.y + xb.w*ef.z + xc.x*ef.w;
                    float d3 = xc.y*ef.y + xc.z*ef.z + xc.w*ef.w;
                    res.x = S2_C * w000.x * x0v.x * ef.x + S2_3_C * w110.x * d0;
                    res.y = S2_C * w000.y * x0v.y * ef.x + S2_3_C * w110.y * d1;
                    res.z = S2_C * w000.z * x0v.z * ef.x + S2_3_C * w110.z * d2;
                    res.w = S2_C * w000.w * x0v.w * ef.x + S2_3_C * w110.w * d3;
                } else {
                    // out1: cols c..c+3 (>=32); m = col-32; u = m/3; j = m%3
                    const int m0 = c - 32;
                    const int ua = m0 / 3;             // m0..m0+3 span ua, ua+1
                    float4 x1v = *(const float4*)&X[c];
                    float w011a = W[32 + ua], w011b = W[32 + ua + 1];
                    float w101a = W[64 + ua], w101b = W[64 + ua + 1];
                    float x0a = X[ua], x0b = X[ua + 1];
                    float r[4];
                    float xs[4] = {x1v.x, x1v.y, x1v.z, x1v.w};
                    #pragma unroll
                    for (int i = 0; i < 4; i++) {
                        int m = m0 + i;
                        int u = m / 3;
                        int j = m - 3 * u;
                        bool hi = (u != ua);
                        float e1j = (j == 0) ? ef.y : ((j == 1) ? ef.z : ef.w);
                        float w011 = hi ? w011b : w011a;
                        float w101 = hi ? w101b : w101a;
                        float x0u  = hi ? x0b  : x0a;
                        r[i] = S2_C * w011 * x0u * e1j + S2_C * w101 * xs[i] * ef.x;
                    }
                    res = make_float4(r[0], r[1], r[2], r[3]);
                }
                float4* dstp = (float4*)(out + (size_t)sDst[e] * NF + c);
                atomicAdd(dstp, res);   // sm_90+ 128-bit red
            }
        }
    }
}

// ---- self-connection: out[n] = concat(n0 @ sc_w0, einsum(n1, sc_w1)) * 1/sqrt(MUL) ----
__global__ __launch_bounds__(128)
void tfn_sc_kernel(const float* __restrict__ node_feat,
                   const float* __restrict__ sc_w0,
                   const float* __restrict__ sc_w1,
                   float* __restrict__ out)
{
    __shared__ float sx[128];
    const int c = threadIdx.x;   // output column 0..127
    float wreg[32];
    int j = 0;
    if (c < 32) {
        #pragma unroll
        for (int u = 0; u < 32; u++) wreg[u] = sc_w0[u * 32 + c];
    } else {
        int m = c - 32;
        int v = m / 3;
        j = m - 3 * v;
        #pragma unroll
        for (int u = 0; u < 32; u++) wreg[u] = sc_w1[u * 32 + v];
    }
    for (int n = blockIdx.x; n < N_NODES; n += gridDim.x) {
        __syncthreads();
        sx[c] = node_feat[(size_t)n * NF + c];
        __syncthreads();
        float acc = 0.0f;
        if (c < 32) {
            #pragma unroll
            for (int u = 0; u < 32; u++) acc += sx[u] * wreg[u];
        } else {
            #pragma unroll
            for (int u = 0; u < 32; u++) acc += sx[32 + 3*u + j] * wreg[u];
        }
        out[(size_t)n * NF + c] = acc * INV_SQRT_MUL_C;
    }
}

extern "C" void kernel_launch(void* const* d_in, const int* in_sizes, int n_in,
                              void* d_out, int out_size)
{
    const int*   edge_index = (const int*)d_in[0];
    const float* node_feat  = (const float*)d_in[1];
    const float* edge_feat  = (const float*)d_in[2];
    const float* edge_embed = (const float*)d_in[3];
    const float* fc_w1 = (const float*)d_in[4];
    const float* fc_b1 = (const float*)d_in[5];
    const float* fc_w2 = (const float*)d_in[6];
    const float* fc_b2 = (const float*)d_in[7];
    const float* fc_w3 = (const float*)d_in[8];
    const float* fc_b3 = (const float*)d_in[9];
    const float* sc_w0 = (const float*)d_in[10];
    const float* sc_w1 = (const float*)d_in[11];
    float* out = (float*)d_out;

    // 1) initialize output with self-connection term
    tfn_sc_kernel<<<2048, 128>>>(node_feat, sc_w0, sc_w1, out);

    // 2) fused edge MLP (tf32 tensor-core) + message + scatter-add
    const size_t smem_bytes = SMEM_FLOATS * sizeof(float);
    cudaFuncSetAttribute(tfn_edge_kernel,
                         cudaFuncAttributeMaxDynamicSharedMemorySize,
                         (int)smem_bytes);
    tfn_edge_kernel<<<304, NTHREADS, smem_bytes>>>(
        edge_index, node_feat, edge_feat, edge_embed,
        fc_w1, fc_b1, fc_w2, fc_b2, fc_w3, fc_b3, out);
}

// round 4
// speedup vs baseline: 1.8404x; 1.1414x over previous
#include <cuda_runtime.h>
#include <cstdint>

#define N_NODES 50000
#define N_EDGES 800000
#define NF 128
#define TILE 32
#define NTHREADS 256
#define NTILES (N_EDGES / TILE)   // 25000 exactly
#define GRID 456                  // 3 CTAs/SM x 152 SMs

#define S2_C 0.7071067811865475f
#define S2_3_C 0.4082482904638631f
#define INV_SQRT_MUL_C 0.17677669529663687f

// ---- shared memory layout (float offsets) ----
// precomputed tf32 B-fragments (fragment-linear, float2 per lane)
#define OFF_FB1 0            // 4kk x 8jg x 32 lanes x float2 = 2048 floats
#define OFF_FB2 2048         // 8kk x 4jg x 32 x float2     = 2048
#define OFF_FB3 4096         // 4kk x 16jg x 32 x float2    = 4096
#define OFF_B1  8192         // 64
#define OFF_B2  8256         // 32
#define OFF_B3  8288         // 128 -> 8416
// activations (conflict-free strides). sX overlaps SE+SH1 ONLY (not SH2),
// so gather can write sX concurrently with GEMM3 reading SH2.
#define SE_STRIDE  36
#define SH1_STRIDE 68
#define SH2_STRIDE 36
#define OFF_SE  8416                      // 32 x 36 = 1152 -> 9568
#define OFF_SH1 9568                      // 32 x 68 = 2176 -> 11744
#define OFF_SX  8416                      // 32 x 128 = 4096 -> 12512 (union SE+SH1+pad)
#define OFF_SH2 12512                     // 32 x 36 = 1152 -> 13664
#define OFF_SW  13664                     // 32 x 132 = 4224 -> 17888
#define OFF_SRC 17888                     // 32 ints
#define OFF_DST 17920                     // 32 ints
#define OFF_EF  17952                     // 32 x 4 -> 18080
#define SMEM_FLOATS 18080                 // 72.3 KB -> 3 CTAs/SM

__device__ __forceinline__ float silu_f(float x) {
    return x * (1.0f / (1.0f + __expf(-x)));
}

// round-to-nearest tf32 conversion, returned as float bits
__device__ __forceinline__ float tf32f(float x) {
    uint32_t r;
    asm("cvt.rna.tf32.f32 %0, %1;" : "=r"(r) : "f"(x));
    return __uint_as_float(r);
}

__device__ __forceinline__ void mma_tf32(float c[4],
                                         uint32_t a0, uint32_t a1, uint32_t a2, uint32_t a3,
                                         uint32_t b0, uint32_t b1) {
    asm volatile("mma.sync.aligned.m16n8k8.row.col.f32.tf32.tf32.f32 "
                 "{%0,%1,%2,%3},{%4,%5,%6,%7},{%8,%9},{%0,%1,%2,%3};"
                 : "+f"(c[0]), "+f"(c[1]), "+f"(c[2]), "+f"(c[3])
                 : "r"(a0), "r"(a1), "r"(a2), "r"(a3), "r"(b0), "r"(b1));
}

extern __shared__ float sm[];

__global__ __launch_bounds__(NTHREADS, 3)
void tfn_edge_kernel(const int* __restrict__ edge_index,
                     const float* __restrict__ node_feat,
                     const float* __restrict__ edge_feat,
                     const float* __restrict__ edge_embed,
                     const float* __restrict__ w1, const float* __restrict__ b1,
                     const float* __restrict__ w2, const float* __restrict__ b2,
                     const float* __restrict__ w3, const float* __restrict__ b3,
                     float* __restrict__ out)
{
    const int t = threadIdx.x;
    const int w = t >> 5, lane = t & 31;
    const int g = lane >> 2, tig = lane & 3;
    const int mr = w >> 2, nq = w & 3;       // 2 row-groups x 4 col-groups

    // ---- precompute tf32 B-fragments (once per CTA, straight from gmem/L2) ----
    // m16n8k8 col-major B frag: b0 = B[8kk+tt][8jg+gg], b1 = B[8kk+tt+4][8jg+gg]
    for (int i = t; i < 1024; i += NTHREADS) {       // W1: 32x64, kk 0..3, jg 0..7
        int kk = i >> 8, jg = (i >> 5) & 7, ln = i & 31;
        int gg = ln >> 2, tt = ln & 3;
        int k0 = 8*kk + tt, n = 8*jg + gg;
        ((float2*)&sm[OFF_FB1])[i] = make_float2(tf32f(w1[k0*64 + n]), tf32f(w1[(k0+4)*64 + n]));
    }
    for (int i = t; i < 1024; i += NTHREADS) {       // W2: 64x32, kk 0..7, jg 0..3
        int kk = i >> 7, jg = (i >> 5) & 3, ln = i & 31;
        int gg = ln >> 2, tt = ln & 3;
        int k0 = 8*kk + tt, n = 8*jg + gg;
        ((float2*)&sm[OFF_FB2])[i] = make_float2(tf32f(w2[k0*32 + n]), tf32f(w2[(k0+4)*32 + n]));
    }
    for (int i = t; i < 2048; i += NTHREADS) {       // W3: 32x128, kk 0..3, jg 0..15
        int kk = i >> 9, jg = (i >> 5) & 15, ln = i & 31;
        int gg = ln >> 2, tt = ln & 3;
        int k0 = 8*kk + tt, n = 8*jg + gg;
        ((float2*)&sm[OFF_FB3])[i] = make_float2(tf32f(w3[k0*128 + n]), tf32f(w3[(k0+4)*128 + n]));
    }
    for (int i = t; i < 64;  i += NTHREADS) sm[OFF_B1 + i] = b1[i];
    for (int i = t; i < 32;  i += NTHREADS) sm[OFF_B2 + i] = b2[i];
    for (int i = t; i < 128; i += NTHREADS) sm[OFF_B3 + i] = b3[i];

    int* sSrc = (int*)&sm[OFF_SRC];
    int* sDst = (int*)&sm[OFF_DST];

    for (int tile = blockIdx.x; tile < NTILES; tile += gridDim.x) {
        const int e0 = tile * TILE;

        __syncthreads();   // prev-iter readers done; also covers precompute on iter 0

        // ---- load indices + edge features ----
        if (t < TILE) {
            sSrc[t] = edge_index[e0 + t];
            sDst[t] = edge_index[N_EDGES + e0 + t];
            ((float4*)&sm[OFF_EF])[t] = ((const float4*)edge_feat)[e0 + t];
        }
        // ---- load embed tile (32x32), tf32-converted; exactly 1 float4/thread ----
        {
            float4 v = ((const float4*)(edge_embed + (size_t)e0 * 32))[t];
            int e = t >> 3, k = 4 * (t & 7);
            *(float4*)&sm[OFF_SE + e * SE_STRIDE + k] =
                make_float4(tf32f(v.x), tf32f(v.y), tf32f(v.z), tf32f(v.w));
        }
        __syncthreads();

        // ---- GEMM1: (32x32)@(32x64) -> +bias -> silu -> tf32 -> sH1 ----
        {
            float c[2][4] = {{0,0,0,0},{0,0,0,0}};
            #pragma unroll
            for (int kk = 0; kk < 4; kk++) {
                const float* Ab = &sm[OFF_SE + (16*mr + g) * SE_STRIDE + 8*kk + tig];
                uint32_t a0 = __float_as_uint(Ab[0]);
                uint32_t a1 = __float_as_uint(Ab[8*SE_STRIDE]);
                uint32_t a2 = __float_as_uint(Ab[4]);
                uint32_t a3 = __float_as_uint(Ab[8*SE_STRIDE + 4]);
                #pragma unroll
                for (int j = 0; j < 2; j++) {
                    float2 b = ((const float2*)&sm[OFF_FB1])[(kk*8 + 2*nq + j)*32 + lane];
                    mma_tf32(c[j], a0, a1, a2, a3, __float_as_uint(b.x), __float_as_uint(b.y));
                }
            }
            #pragma unroll
            for (int j = 0; j < 2; j++) {
                int n0 = 16*nq + 8*j + 2*tig;
                float2 bb = *(const float2*)&sm[OFF_B1 + n0];
                int r0 = 16*mr + g;
                *(float2*)&sm[OFF_SH1 + r0*SH1_STRIDE + n0] =
                    make_float2(tf32f(silu_f(c[j][0] + bb.x)), tf32f(silu_f(c[j][1] + bb.y)));
                *(float2*)&sm[OFF_SH1 + (r0+8)*SH1_STRIDE + n0] =
                    make_float2(tf32f(silu_f(c[j][2] + bb.x)), tf32f(silu_f(c[j][3] + bb.y)));
            }
        }
        __syncthreads();

        // ---- GEMM2: (32x64)@(64x32) -> +bias -> silu -> tf32 -> sH2 ----
        {
            float c[4] = {0,0,0,0};
            #pragma unroll
            for (int kk = 0; kk < 8; kk++) {
                const float* Ab = &sm[OFF_SH1 + (16*mr + g) * SH1_STRIDE + 8*kk + tig];
                uint32_t a0 = __float_as_uint(Ab[0]);
                uint32_t a1 = __float_as_uint(Ab[8*SH1_STRIDE]);
                uint32_t a2 = __float_as_uint(Ab[4]);
                uint32_t a3 = __float_as_uint(Ab[8*SH1_STRIDE + 4]);
                float2 b = ((const float2*)&sm[OFF_FB2])[(kk*4 + nq)*32 + lane];
                mma_tf32(c, a0, a1, a2, a3, __float_as_uint(b.x), __float_as_uint(b.y));
            }
            int n0 = 8*nq + 2*tig;
            float2 bb = *(const float2*)&sm[OFF_B2 + n0];
            int r0 = 16*mr + g;
            *(float2*)&sm[OFF_SH2 + r0*SH2_STRIDE + n0] =
                make_float2(tf32f(silu_f(c[0] + bb.x)), tf32f(silu_f(c[1] + bb.y)));
            *(float2*)&sm[OFF_SH2 + (r0+8)*SH2_STRIDE + n0] =
                make_float2(tf32f(silu_f(c[2] + bb.x)), tf32f(silu_f(c[3] + bb.y)));
        }
        __syncthreads();

        // ---- GEMM3: (32x32)@(32x128) -> +bias -> sW, overlapped with gather LDG ----
        {
            // issue gather loads first: LDG latency hides behind the 16 MMAs
            float4 xr[4];
            #pragma unroll
            for (int i = 0; i < 4; i++) {
                const float4* srcp = (const float4*)(node_feat + (size_t)sSrc[w + 8*i] * NF);
                xr[i] = __ldg(&srcp[lane]);
            }

            float c[4][4] = {{0,0,0,0},{0,0,0,0},{0,0,0,0},{0,0,0,0}};
            #pragma unroll
            for (int kk = 0; kk < 4; kk++) {
                const float* Ab = &sm[OFF_SH2 + (16*mr + g) * SH2_STRIDE + 8*kk + tig];
                uint32_t a0 = __float_as_uint(Ab[0]);
                uint32_t a1 = __float_as_uint(Ab[8*SH2_STRIDE]);
                uint32_t a2 = __float_as_uint(Ab[4]);
                uint32_t a3 = __float_as_uint(Ab[8*SH2_STRIDE + 4]);
                #pragma unroll
                for (int j = 0; j < 4; j++) {
                    float2 b = ((const float2*)&sm[OFF_FB3])[(kk*16 + 4*nq + j)*32 + lane];
                    mma_tf32(c[j], a0, a1, a2, a3, __float_as_uint(b.x), __float_as_uint(b.y));
                }
            }
            #pragma unroll
            for (int j = 0; j < 4; j++) {
                int n0 = 32*nq + 8*j + 2*tig;
                float2 bb = *(const float2*)&sm[OFF_B3 + n0];
                int r0 = 16*mr + g;
                *(float2*)&sm[OFF_SW + r0*132 + n0] = make_float2(c[j][0] + bb.x, c[j][1] + bb.y);
                *(float2*)&sm[OFF_SW + (r0+8)*132 + n0] = make_float2(c[j][2] + bb.x, c[j][3] + bb.y);
            }

            // commit gathered rows to sX (overlaps SE+SH1, both dead now)
            #pragma unroll
            for (int i = 0; i < 4; i++)
                ((float4*)&sm[OFF_SX + (w + 8*i) * NF])[lane] = xr[i];
        }
        __syncthreads();

        // ---- message construction + vector atomic scatter ----
        {
            const int c = 4 * lane;
            #pragma unroll
            for (int e = w; e < TILE; e += 8) {
                float4 ef = ((const float4*)&sm[OFF_EF])[e];   // e0, e1x, e1y, e1z
                const float* X = &sm[OFF_SX + e * NF];
                const float* W = &sm[OFF_SW + e * 132];
                float4 res;
                if (lane < 8) {
                    // out0: cols c..c+3 (<32), u == col
                    float4 w000 = *(const float4*)&W[c];
                    float4 w110 = *(const float4*)&W[96 + c];
                    float4 x0v  = *(const float4*)&X[c];
                    float4 xa = *(const float4*)&X[32 + 12*lane];
                    float4 xb = *(const float4*)&X[32 + 12*lane + 4];
                    float4 xc = *(const float4*)&X[32 + 12*lane + 8];
                    float d0 = xa.x*ef.y + xa.y*ef.z + xa.z*ef.w;
                    float d1 = xa.w*ef.y + xb.x*ef.z + xb.y*ef.w;
                    float d2 = xb.z*ef.y + xb.w*ef.z + xc.x*ef.w;
                    float d3 = xc.y*ef.y + xc.z*ef.z + xc.w*ef.w;
                    res.x = S2_C * w000.x * x0v.x * ef.x + S2_3_C * w110.x * d0;
                    res.y = S2_C * w000.y * x0v.y * ef.x + S2_3_C * w110.y * d1;
                    res.z = S2_C * w000.z * x0v.z * ef.x + S2_3_C * w110.z * d2;
                    res.w = S2_C * w000.w * x0v.w * ef.x + S2_3_C * w110.w * d3;
                } else {
                    // out1: cols c..c+3 (>=32); m = col-32; u = m/3; j = m%3
                    const int m0 = c - 32;
                    const int ua = m0 / 3;             // m0..m0+3 span ua, ua+1
                    float4 x1v = *(const float4*)&X[c];
                    float w011a = W[32 + ua], w011b = W[32 + ua + 1];
                    float w101a = W[64 + ua], w101b = W[64 + ua + 1];
                    float x0a = X[ua], x0b = X[ua + 1];
                    float r[4];
                    float xs[4] = {x1v.x, x1v.y, x1v.z, x1v.w};
                    #pragma unroll
                    for (int i = 0; i < 4; i++) {
                        int m = m0 + i;
                        int u = m / 3;
                        int j = m - 3 * u;
                        bool hi = (u != ua);
                        float e1j = (j == 0) ? ef.y : ((j == 1) ? ef.z : ef.w);
                        float w011 = hi ? w011b : w011a;
                        float w101 = hi ? w101b : w101a;
                        float x0u  = hi ? x0b  : x0a;
                        r[i] = S2_C * w011 * x0u * e1j + S2_C * w101 * xs[i] * ef.x;
                    }
                    res = make_float4(r[0], r[1], r[2], r[3]);
                }
                float4* dstp = (float4*)(out + (size_t)sDst[e] * NF + c);
                atomicAdd(dstp, res);   // sm_90+ 128-bit red
            }
        }
    }
}

// ---- self-connection: out[n] = concat(n0 @ sc_w0, einsum(n1, sc_w1)) * 1/sqrt(MUL) ----
__global__ __launch_bounds__(128)
void tfn_sc_kernel(const float* __restrict__ node_feat,
                   const float* __restrict__ sc_w0,
                   const float* __restrict__ sc_w1,
                   float* __restrict__ out)
{
    __shared__ float sx[128];
    const int c = threadIdx.x;   // output column 0..127
    float wreg[32];
    int j = 0;
    if (c < 32) {
        #pragma unroll
        for (int u = 0; u < 32; u++) wreg[u] = sc_w0[u * 32 + c];
    } else {
        int m = c - 32;
        int v = m / 3;
        j = m - 3 * v;
        #pragma unroll
        for (int u = 0; u < 32; u++) wreg[u] = sc_w1[u * 32 + v];
    }
    for (int n = blockIdx.x; n < N_NODES; n += gridDim.x) {
        __syncthreads();
        sx[c] = node_feat[(size_t)n * NF + c];
        __syncthreads();
        float acc = 0.0f;
        if (c < 32) {
            #pragma unroll
            for (int u = 0; u < 32; u++) acc += sx[u] * wreg[u];
        } else {
            #pragma unroll
            for (int u = 0; u < 32; u++) acc += sx[32 + 3*u + j] * wreg[u];
        }
        out[(size_t)n * NF + c] = acc * INV_SQRT_MUL_C;
    }
}

extern "C" void kernel_launch(void* const* d_in, const int* in_sizes, int n_in,
                              void* d_out, int out_size)
{
    const int*   edge_index = (const int*)d_in[0];
    const float* node_feat  = (const float*)d_in[1];
    const float* edge_feat  = (const float*)d_in[2];
    const float* edge_embed = (const float*)d_in[3];
    const float* fc_w1 = (const float*)d_in[4];
    const float* fc_b1 = (const float*)d_in[5];
    const float* fc_w2 = (const float*)d_in[6];
    const float* fc_b2 = (const float*)d_in[7];
    const float* fc_w3 = (const float*)d_in[8];
    const float* fc_b3 = (const float*)d_in[9];
    const float* sc_w0 = (const float*)d_in[10];
    const float* sc_w1 = (const float*)d_in[11];
    float* out = (float*)d_out;

    // 1) initialize output with self-connection term
    tfn_sc_kernel<<<2048, 128>>>(node_feat, sc_w0, sc_w1, out);

    // 2) fused edge MLP (tf32 tensor-core) + message + scatter-add
    const size_t smem_bytes = SMEM_FLOATS * sizeof(float);
    cudaFuncSetAttribute(tfn_edge_kernel,
                         cudaFuncAttributeMaxDynamicSharedMemorySize,
                         (int)smem_bytes);
    tfn_edge_kernel<<<GRID, NTHREADS, smem_bytes>>>(
        edge_index, node_feat, edge_feat, edge_embed,
        fc_w1, fc_b1, fc_w2, fc_b2, fc_w3, fc_b3, out);
}